// round 4
// baseline (speedup 1.0000x reference)
#include <cuda_runtime.h>

// Problem constants
#define BB 2048
#define TT 200
#define DD 4
#define HH 256
#define GG 1024        // 4*H, gate order i,f,g,o
#define MM 16          // batch rows per CTA
#define NCTA (BB / MM) // 128 CTAs
#define MH 8           // rows per thread (one batch half)
#define OO 6
#define HROW 18        // u64 (dup-pair) slots per h row: 16 used + 2 pad (144B, 16B-aligned)
#define SH_LAYER (2 * HH * HROW)  // u64 count for one double-buffered layer

typedef unsigned long long u64;

// Gate-pair-interleaved transposed weights: [k][pp][j], pp=0 -> (w_i,w_f), pp=1 -> (w_g,w_o)
__device__ u64 g_Wp_hh0[HH * 2 * HH];
__device__ u64 g_Wp_ih1[HH * 2 * HH];
__device__ u64 g_Wp_hh1[HH * 2 * HH];
__device__ float g_b0[GG];
__device__ float g_b1[GG];

// ---- packed f32x2 helpers ----
__device__ __forceinline__ u64 fma2(u64 a, u64 b, u64 c) {
    u64 d;
    asm("fma.rn.f32x2 %0, %1, %2, %3;" : "=l"(d) : "l"(a), "l"(b), "l"(c));
    return d;
}
__device__ __forceinline__ u64 pack2(float a, float b) {
    u64 d;
    asm("mov.b64 %0, {%1, %2};" : "=l"(d)
        : "r"(__float_as_uint(a)), "r"(__float_as_uint(b)));
    return d;
}
__device__ __forceinline__ void unpack2(u64 v, float& a, float& b) {
    unsigned x, y;
    asm("mov.b64 {%0, %1}, %2;" : "=r"(x), "=r"(y) : "l"(v));
    a = __uint_as_float(x);
    b = __uint_as_float(y);
}
__device__ __forceinline__ float sigf(float x) {
    return 1.0f / (1.0f + __expf(-x));
}

// -------- prep: build gate-pair-interleaved transposed weights + combined biases --------
__global__ void prep_kernel(const float* __restrict__ W_hh0,
                            const float* __restrict__ W_ih1,
                            const float* __restrict__ W_hh1,
                            const float* __restrict__ b_ih0,
                            const float* __restrict__ b_hh0,
                            const float* __restrict__ b_ih1,
                            const float* __restrict__ b_hh1) {
    int idx = blockIdx.x * blockDim.x + threadIdx.x;
    int stride = gridDim.x * blockDim.x;
    for (int t = idx; t < HH * 2 * HH; t += stride) {
        int j = t & (HH - 1);
        int pp = (t >> 8) & 1;
        int k = t >> 9;
        int g0 = 2 * pp * HH + j;   // gate i (pp=0) or g (pp=1)
        int g1 = g0 + HH;           // gate f (pp=0) or o (pp=1)
        g_Wp_hh0[t] = pack2(W_hh0[g0 * HH + k], W_hh0[g1 * HH + k]);
        g_Wp_ih1[t] = pack2(W_ih1[g0 * HH + k], W_ih1[g1 * HH + k]);
        g_Wp_hh1[t] = pack2(W_hh1[g0 * HH + k], W_hh1[g1 * HH + k]);
    }
    if (idx < GG) {
        g_b0[idx] = b_ih0[idx] + b_hh0[idx];
        g_b1[idx] = b_ih1[idx] + b_hh1[idx];
    }
}

// -------- main LSTM kernel: 512 threads = 256 hidden units x 2 batch halves --------
__global__ __launch_bounds__(512, 1)
void lstm_kernel(const float* __restrict__ x,
                 const float* __restrict__ W_ih0,
                 const float* __restrict__ W_fc,
                 const float* __restrict__ b_fc,
                 float* __restrict__ out) {
    extern __shared__ u64 dsm[];
    u64* sh1 = dsm;                    // [2][HH][HROW] layer0 h, dup pairs
    u64* sh2 = dsm + SH_LAYER;         // [2][HH][HROW] layer1 h
    float* xs = (float*)(dsm + 2 * SH_LAYER);  // [MM][DD]

    const int tid  = threadIdx.x;
    const int j    = tid & (HH - 1);   // hidden unit
    const int half = tid >> 8;         // batch half (warp-uniform)
    const int mb   = half * MH;        // first row (= dup-pair slot) for this thread
    const int row0 = blockIdx.x * MM;

    // Per-thread constants
    float wih0[4][DD];
    float bi0 = g_b0[j], bf0 = g_b0[j + HH], bg0 = g_b0[j + 2 * HH], bo0 = g_b0[j + 3 * HH];
    float bi1 = g_b1[j], bf1 = g_b1[j + HH], bg1 = g_b1[j + 2 * HH], bo1 = g_b1[j + 3 * HH];
#pragma unroll
    for (int q = 0; q < 4; q++)
#pragma unroll
        for (int d = 0; d < DD; d++)
            wih0[q][d] = W_ih0[(j + q * HH) * DD + d];

    float c1[MH], c2[MH];
#pragma unroll
    for (int m = 0; m < MH; m++) {
        c1[m] = 0.0f;
        c2[m] = 0.0f;
        sh1[j * HROW + mb + m] = 0ull;   // buffer 0
        sh2[j * HROW + mb + m] = 0ull;
    }

    // prefetch x for t=0
    float xreg = 0.0f;
    if (tid < MM * DD)
        xreg = x[(row0 + (tid >> 2)) * (TT * DD) + (tid & 3)];
    __syncthreads();

    for (int t = 0; t < TT; t++) {
        const int inb = t & 1;
        const int outb = inb ^ 1;
        const u64* h1in = sh1 + inb * (HH * HROW);
        u64* h1out      = sh1 + outb * (HH * HROW);
        const u64* h2in = sh2 + inb * (HH * HROW);
        u64* h2out      = sh2 + outb * (HH * HROW);

        if (tid < MM * DD) xs[tid] = xreg;
        __syncthreads();  // B1: xs + prev-step h2 writes visible

        // ================= Layer 0 =================
        u64 aif[MH], ago[MH];
#pragma unroll
        for (int m = 0; m < MH; m++) {
            float zi = bi0, zf = bf0, zg = bg0, zo = bo0;
#pragma unroll
            for (int d = 0; d < DD; d++) {
                float xv = xs[(mb + m) * DD + d];
                zi = fmaf(wih0[0][d], xv, zi);
                zf = fmaf(wih0[1][d], xv, zf);
                zg = fmaf(wih0[2][d], xv, zg);
                zo = fmaf(wih0[3][d], xv, zo);
            }
            aif[m] = pack2(zi, zf);
            ago[m] = pack2(zg, zo);
        }

        {
            const u64* p = g_Wp_hh0 + j;
#pragma unroll 4
            for (int k = 0; k < HH; k++) {
                u64 wif = p[0];
                u64 wgo = p[HH];
                p += 2 * HH;
                const longlong2* hr = (const longlong2*)(h1in + k * HROW + mb);
                longlong2 h01 = hr[0], h23 = hr[1], h45 = hr[2], h67 = hr[3];
                aif[0] = fma2(wif, (u64)h01.x, aif[0]); ago[0] = fma2(wgo, (u64)h01.x, ago[0]);
                aif[1] = fma2(wif, (u64)h01.y, aif[1]); ago[1] = fma2(wgo, (u64)h01.y, ago[1]);
                aif[2] = fma2(wif, (u64)h23.x, aif[2]); ago[2] = fma2(wgo, (u64)h23.x, ago[2]);
                aif[3] = fma2(wif, (u64)h23.y, aif[3]); ago[3] = fma2(wgo, (u64)h23.y, ago[3]);
                aif[4] = fma2(wif, (u64)h45.x, aif[4]); ago[4] = fma2(wgo, (u64)h45.x, ago[4]);
                aif[5] = fma2(wif, (u64)h45.y, aif[5]); ago[5] = fma2(wgo, (u64)h45.y, ago[5]);
                aif[6] = fma2(wif, (u64)h67.x, aif[6]); ago[6] = fma2(wgo, (u64)h67.x, ago[6]);
                aif[7] = fma2(wif, (u64)h67.y, aif[7]); ago[7] = fma2(wgo, (u64)h67.y, ago[7]);
            }
        }

        // activations + cell update, write dup'd h1
#pragma unroll
        for (int m = 0; m < MH; m++) {
            float zi, zf, zg, zo;
            unpack2(aif[m], zi, zf);
            unpack2(ago[m], zg, zo);
            float ig = sigf(zi), fg = sigf(zf), gg = tanhf(zg), og = sigf(zo);
            float c = fmaf(fg, c1[m], ig * gg);
            c1[m] = c;
            float h = og * tanhf(c);
            h1out[j * HROW + mb + m] = pack2(h, h);
        }

        // prefetch x for t+1 (hidden under layer-1 compute)
        if (tid < MM * DD && t + 1 < TT)
            xreg = x[(row0 + (tid >> 2)) * (TT * DD) + (t + 1) * DD + (tid & 3)];

        __syncthreads();  // B2: h1out visible

        // ================= Layer 1 =================
#pragma unroll
        for (int m = 0; m < MH; m++) {
            aif[m] = pack2(bi1, bf1);
            ago[m] = pack2(bg1, bo1);
        }

        {
            const u64* pi = g_Wp_ih1 + j;
            const u64* ph = g_Wp_hh1 + j;
#pragma unroll 2
            for (int k = 0; k < HH; k++) {
                u64 wiif = pi[0];
                u64 wigo = pi[HH];
                pi += 2 * HH;
                u64 whif = ph[0];
                u64 whgo = ph[HH];
                ph += 2 * HH;
                const longlong2* ar = (const longlong2*)(h1out + k * HROW + mb);
                const longlong2* br = (const longlong2*)(h2in + k * HROW + mb);
                longlong2 a01 = ar[0], a23 = ar[1], a45 = ar[2], a67 = ar[3];
                longlong2 b01 = br[0], b23 = br[1], b45 = br[2], b67 = br[3];
                aif[0] = fma2(wiif, (u64)a01.x, aif[0]); ago[0] = fma2(wigo, (u64)a01.x, ago[0]);
                aif[0] = fma2(whif, (u64)b01.x, aif[0]); ago[0] = fma2(whgo, (u64)b01.x, ago[0]);
                aif[1] = fma2(wiif, (u64)a01.y, aif[1]); ago[1] = fma2(wigo, (u64)a01.y, ago[1]);
                aif[1] = fma2(whif, (u64)b01.y, aif[1]); ago[1] = fma2(whgo, (u64)b01.y, ago[1]);
                aif[2] = fma2(wiif, (u64)a23.x, aif[2]); ago[2] = fma2(wigo, (u64)a23.x, ago[2]);
                aif[2] = fma2(whif, (u64)b23.x, aif[2]); ago[2] = fma2(whgo, (u64)b23.x, ago[2]);
                aif[3] = fma2(wiif, (u64)a23.y, aif[3]); ago[3] = fma2(wigo, (u64)a23.y, ago[3]);
                aif[3] = fma2(whif, (u64)b23.y, aif[3]); ago[3] = fma2(whgo, (u64)b23.y, ago[3]);
                aif[4] = fma2(wiif, (u64)a45.x, aif[4]); ago[4] = fma2(wigo, (u64)a45.x, ago[4]);
                aif[4] = fma2(whif, (u64)b45.x, aif[4]); ago[4] = fma2(whgo, (u64)b45.x, ago[4]);
                aif[5] = fma2(wiif, (u64)a45.y, aif[5]); ago[5] = fma2(wigo, (u64)a45.y, ago[5]);
                aif[5] = fma2(whif, (u64)b45.y, aif[5]); ago[5] = fma2(whgo, (u64)b45.y, ago[5]);
                aif[6] = fma2(wiif, (u64)a67.x, aif[6]); ago[6] = fma2(wigo, (u64)a67.x, ago[6]);
                aif[6] = fma2(whif, (u64)b67.x, aif[6]); ago[6] = fma2(whgo, (u64)b67.x, ago[6]);
                aif[7] = fma2(wiif, (u64)a67.y, aif[7]); ago[7] = fma2(wigo, (u64)a67.y, ago[7]);
                aif[7] = fma2(whif, (u64)b67.y, aif[7]); ago[7] = fma2(whgo, (u64)b67.y, ago[7]);
            }
        }

#pragma unroll
        for (int m = 0; m < MH; m++) {
            float zi, zf, zg, zo;
            unpack2(aif[m], zi, zf);
            unpack2(ago[m], zg, zo);
            float ig = sigf(zi), fg = sigf(zf), gg = tanhf(zg), og = sigf(zo);
            float c = fmaf(fg, c2[m], ig * gg);
            c2[m] = c;
            float h = og * tanhf(c);
            h2out[j * HROW + mb + m] = pack2(h, h);
        }
        // next iteration's B1 orders h2out writes before next layer-1 reads
    }
    __syncthreads();

    // ---- FC epilogue ----
    const int fb = 1 ^ ((TT - 1) & 1);  // final h2 buffer index (0 for TT=200)
    if (tid < MM * OO) {
        int m = tid / OO;
        int o = tid % OO;
        const float* h2f = (const float*)(sh2 + fb * (HH * HROW));
        float s = b_fc[o];
#pragma unroll 4
        for (int k = 0; k < HH; k++)
            s = fmaf(h2f[k * (2 * HROW) + 2 * m], W_fc[o * HH + k], s);
        out[(row0 + m) * OO + o] = s;
    }
}

extern "C" void kernel_launch(void* const* d_in, const int* in_sizes, int n_in,
                              void* d_out, int out_size) {
    const float* x     = (const float*)d_in[0];
    const float* W_ih0 = (const float*)d_in[1];
    const float* W_hh0 = (const float*)d_in[2];
    const float* b_ih0 = (const float*)d_in[3];
    const float* b_hh0 = (const float*)d_in[4];
    const float* W_ih1 = (const float*)d_in[5];
    const float* W_hh1 = (const float*)d_in[6];
    const float* b_ih1 = (const float*)d_in[7];
    const float* b_hh1 = (const float*)d_in[8];
    const float* W_fc  = (const float*)d_in[9];
    const float* b_fc  = (const float*)d_in[10];
    float* out = (float*)d_out;

    const int smem_bytes = (2 * SH_LAYER) * 8 + MM * DD * 4;
    cudaFuncSetAttribute(lstm_kernel, cudaFuncAttributeMaxDynamicSharedMemorySize,
                         smem_bytes);

    prep_kernel<<<256, 256>>>(W_hh0, W_ih1, W_hh1, b_ih0, b_hh0, b_ih1, b_hh1);
    lstm_kernel<<<NCTA, 512, smem_bytes>>>(x, W_ih0, W_fc, b_fc, out);
}